// round 1
// baseline (speedup 1.0000x reference)
#include <cuda_runtime.h>
#include <cstdint>
#include <math.h>

// Problem constants
#define T_TOK 4096
#define D_DIM 2048
#define FF_DIM 8192
#define E_EXP 16
#define CAP 640          // ceil(1.25 * 2 * 4096 / 16)

// ---------------------------------------------------------------------------
// Scratch (device globals — allocation-free kernel_launch)
// ---------------------------------------------------------------------------
__device__ float g_Xe[(size_t)E_EXP * CAP * D_DIM];   //  84 MB dispatched tokens
__device__ float g_h [(size_t)E_EXP * CAP * FF_DIM];  // 335 MB gelu(Xe@W1+b1)
__device__ float g_Ye[(size_t)E_EXP * CAP * D_DIM];   //  84 MB expert outputs
__device__ int   g_eidx[T_TOK * 2];
__device__ float g_gate[T_TOK * 2];
__device__ int   g_pos [T_TOK * 2];

// ---------------------------------------------------------------------------
// Helpers
// ---------------------------------------------------------------------------
__device__ __forceinline__ float to_tf32(float x) {
    uint32_t u = __float_as_uint(x);
    asm volatile("cvt.rna.tf32.f32 %0, %1;" : "=r"(u) : "r"(u));
    return __uint_as_float(u);
}

__device__ __forceinline__ uint32_t cvt_tf32_u(float x) {
    uint32_t u = __float_as_uint(x);
    asm volatile("cvt.rna.tf32.f32 %0, %1;" : "=r"(u) : "r"(u));
    return u;
}

__device__ __forceinline__ float gelu_exact(float v) {
    return 0.5f * v * (1.0f + erff(v * 0.70710678118654752f));
}

__device__ __forceinline__ void cp_async16(void* smem, const void* gmem) {
    uint32_t s = (uint32_t)__cvta_generic_to_shared(smem);
    asm volatile("cp.async.cg.shared.global [%0], [%1], 16;\n" :: "r"(s), "l"(gmem));
}

__device__ __forceinline__ void mma_tf32(float (&c)[4], const uint32_t (&a)[4],
                                         const uint32_t (&b)[2]) {
    asm volatile(
        "mma.sync.aligned.m16n8k8.row.col.f32.tf32.tf32.f32 "
        "{%0,%1,%2,%3}, {%4,%5,%6,%7}, {%8,%9}, {%0,%1,%2,%3};"
        : "+f"(c[0]), "+f"(c[1]), "+f"(c[2]), "+f"(c[3])
        : "r"(a[0]), "r"(a[1]), "r"(a[2]), "r"(a[3]), "r"(b[0]), "r"(b[1]));
}

// ---------------------------------------------------------------------------
// 1) Gating: one warp per token. logits = x @ Wg; top-2; normalized gates.
//    (softmax denominator cancels in the top-2 renormalization)
// ---------------------------------------------------------------------------
__global__ void gate_kernel(const float* __restrict__ x, const float* __restrict__ Wg) {
    int t = (blockIdx.x * blockDim.x + threadIdx.x) >> 5;
    int lane = threadIdx.x & 31;
    if (t >= T_TOK) return;
    const float* xr = x + (size_t)t * D_DIM;

    float acc[E_EXP];
#pragma unroll
    for (int e = 0; e < E_EXP; e++) acc[e] = 0.0f;

    for (int d = lane; d < D_DIM; d += 32) {
        float xv = xr[d];
        const float4* wg = (const float4*)(Wg + (size_t)d * E_EXP);
#pragma unroll
        for (int q = 0; q < 4; q++) {
            float4 w = wg[q];
            acc[q * 4 + 0] += xv * w.x;
            acc[q * 4 + 1] += xv * w.y;
            acc[q * 4 + 2] += xv * w.z;
            acc[q * 4 + 3] += xv * w.w;
        }
    }
#pragma unroll
    for (int e = 0; e < E_EXP; e++) {
        float v = acc[e];
#pragma unroll
        for (int o = 16; o > 0; o >>= 1) v += __shfl_xor_sync(0xffffffffu, v, o);
        acc[e] = v;
    }
    if (lane == 0) {
        int i1 = 0; float v1 = acc[0];
#pragma unroll
        for (int e = 1; e < E_EXP; e++) if (acc[e] > v1) { v1 = acc[e]; i1 = e; }
        int i2 = -1; float v2 = -1e30f;
#pragma unroll
        for (int e = 0; e < E_EXP; e++)
            if (e != i1 && acc[e] > v2) { v2 = acc[e]; i2 = e; }
        float r  = expf(v2 - v1);       // p2/p1
        float g1 = 1.0f / (1.0f + r);
        float g2 = r * g1;
        g_eidx[t * 2 + 0] = i1;  g_eidx[t * 2 + 1] = i2;
        g_gate[t * 2 + 0] = g1;  g_gate[t * 2 + 1] = g2;
    }
}

// ---------------------------------------------------------------------------
// 2) Ordered capacity scan. 1 block, 16 warps; warp w owns expert w.
//    Token-order ranks via ballot/popc. Slot-1 ranks offset by count0[e].
// ---------------------------------------------------------------------------
__global__ void scan_kernel() {
    int w = threadIdx.x >> 5;     // expert id (0..15)
    int lane = threadIdx.x & 31;
    int cnt = 0;
    for (int t0 = 0; t0 < T_TOK; t0 += 32) {
        int t = t0 + lane;
        bool m = (g_eidx[t * 2 + 0] == w);
        unsigned mask = __ballot_sync(0xffffffffu, m);
        if (m) g_pos[t * 2 + 0] = cnt + __popc(mask & ((1u << lane) - 1u));
        cnt += __popc(mask);
    }
    // slot-1 positions start at count0[w]
    for (int t0 = 0; t0 < T_TOK; t0 += 32) {
        int t = t0 + lane;
        bool m = (g_eidx[t * 2 + 1] == w);
        unsigned mask = __ballot_sync(0xffffffffu, m);
        if (m) g_pos[t * 2 + 1] = cnt + __popc(mask & ((1u << lane) - 1u));
        cnt += __popc(mask);
    }
}

// ---------------------------------------------------------------------------
// 3) Dispatch: scatter token rows into Xe (tf32-rounded at the source so the
//    GEMM A-fragments need no conversion).
// ---------------------------------------------------------------------------
__global__ void dispatch_kernel(const float* __restrict__ x) {
    int t = blockIdx.x;
    const float4* xr = (const float4*)(x + (size_t)t * D_DIM);
#pragma unroll
    for (int k = 0; k < 2; k++) {
        int p = g_pos[t * 2 + k];
        if (p < CAP) {
            int e = g_eidx[t * 2 + k];
            float4* dst = (float4*)(g_Xe + ((size_t)e * CAP + p) * D_DIM);
            for (int i = threadIdx.x; i < D_DIM / 4; i += blockDim.x) {
                float4 v = xr[i];
                v.x = to_tf32(v.x); v.y = to_tf32(v.y);
                v.z = to_tf32(v.z); v.w = to_tf32(v.w);
                dst[i] = v;
            }
        }
    }
}

// ---------------------------------------------------------------------------
// 4) Grouped GEMM (per-expert), TF32 mma.sync m16n8k8.
//    BM=BN=128, BK=16, 256 threads = 8 warps (2x4), warp tile 64x32.
//    cp.async double-buffered. A smem m-major stride 20 (conflict-free frag
//    loads), B smem k-major stride 136 (conflict-free).
//    blockIdx.x = m-tile (fast) so concurrent CTAs share the B slab in L2.
// ---------------------------------------------------------------------------
template<int KDIM, int NDIM, bool DOGELU>
__global__ void __launch_bounds__(256)
gemm_kernel(const float* __restrict__ A, const float* __restrict__ Bw,
            const float* __restrict__ bias, float* __restrict__ Cout) {
    constexpr int BM = 128, BN = 128, BK = 16;
    constexpr int KT = KDIM / BK;
    const int mt = blockIdx.x, nt = blockIdx.y, e = blockIdx.z;

    __shared__ float As[2][BM][20];
    __shared__ float Bs[2][BK][136];

    const int tid = threadIdx.x, lane = tid & 31, wid = tid >> 5;
    const int wm = (wid >> 2) * 64, wn = (wid & 3) * 32;

    const float* Ae = A + ((size_t)e * CAP + (size_t)mt * BM) * KDIM;
    const float* Be = Bw + (size_t)e * KDIM * NDIM + (size_t)nt * BN;

    const int arow = tid >> 2, acol = (tid & 3) * 4;
    const int brow = tid >> 5, bcol = (tid & 31) * 4;

    float acc[4][4][4];
#pragma unroll
    for (int i = 0; i < 4; i++)
#pragma unroll
        for (int j = 0; j < 4; j++)
#pragma unroll
            for (int q = 0; q < 4; q++) acc[i][j][q] = 0.0f;

    auto load_stage = [&](int s, int kt) {
        const float* ag = Ae + (size_t)arow * KDIM + kt * BK + acol;
        cp_async16(&As[s][arow][acol], ag);
        cp_async16(&As[s][arow + 64][acol], ag + (size_t)64 * KDIM);
        const float* bg = Be + (size_t)(kt * BK + brow) * NDIM + bcol;
        cp_async16(&Bs[s][brow][bcol], bg);
        cp_async16(&Bs[s][brow + 8][bcol], bg + (size_t)8 * NDIM);
    };

    load_stage(0, 0);
    asm volatile("cp.async.commit_group;\n" ::: "memory");

    for (int kt = 0; kt < KT; kt++) {
        const int s = kt & 1;
        asm volatile("cp.async.wait_group 0;\n" ::: "memory");
        __syncthreads();
        if (kt + 1 < KT) {
            load_stage(s ^ 1, kt + 1);
            asm volatile("cp.async.commit_group;\n" ::: "memory");
        }
#pragma unroll
        for (int ks = 0; ks < 2; ks++) {
            const int kk = ks * 8 + (lane & 3);
            const int r  = lane >> 2;
            uint32_t a[4][4], b[4][2];
#pragma unroll
            for (int f = 0; f < 4; f++) {
                const int m = wm + f * 16 + r;
                a[f][0] = __float_as_uint(As[s][m][kk]);        // pre-rounded tf32
                a[f][1] = __float_as_uint(As[s][m + 8][kk]);
                a[f][2] = __float_as_uint(As[s][m][kk + 4]);
                a[f][3] = __float_as_uint(As[s][m + 8][kk + 4]);
            }
#pragma unroll
            for (int f = 0; f < 4; f++) {
                const int n = wn + f * 8 + r;
                b[f][0] = cvt_tf32_u(Bs[s][kk][n]);
                b[f][1] = cvt_tf32_u(Bs[s][kk + 4][n]);
            }
#pragma unroll
            for (int fm = 0; fm < 4; fm++)
#pragma unroll
                for (int fn = 0; fn < 4; fn++)
                    mma_tf32(acc[fm][fn], a[fm], b[fn]);
        }
    }

    // epilogue: +bias, optional exact-GELU (+tf32 round for GEMM2 consumption)
    const float* be = bias + (size_t)e * NDIM + (size_t)nt * BN;
    float* Ce = Cout + ((size_t)e * CAP + (size_t)mt * BM) * NDIM + (size_t)nt * BN;
#pragma unroll
    for (int fm = 0; fm < 4; fm++) {
#pragma unroll
        for (int fn = 0; fn < 4; fn++) {
            int row = wm + fm * 16 + (lane >> 2);
            int col = wn + fn * 8 + (lane & 3) * 2;
            float2 bb = *(const float2*)(be + col);
            float v0 = acc[fm][fn][0] + bb.x;
            float v1 = acc[fm][fn][1] + bb.y;
            float v2 = acc[fm][fn][2] + bb.x;
            float v3 = acc[fm][fn][3] + bb.y;
            if (DOGELU) {
                v0 = to_tf32(gelu_exact(v0)); v1 = to_tf32(gelu_exact(v1));
                v2 = to_tf32(gelu_exact(v2)); v3 = to_tf32(gelu_exact(v3));
            }
            *(float2*)(Ce + (size_t)row * NDIM + col)       = make_float2(v0, v1);
            *(float2*)(Ce + (size_t)(row + 8) * NDIM + col) = make_float2(v2, v3);
        }
    }
}

// ---------------------------------------------------------------------------
// 5) Combine: y[t] = g0*Ye[e0,c0] + g1*Ye[e1,c1] (gates zeroed past capacity)
// ---------------------------------------------------------------------------
__global__ void combine_kernel(float* __restrict__ out) {
    int t = blockIdx.x;
    int e0 = g_eidx[t * 2 + 0], e1 = g_eidx[t * 2 + 1];
    int p0 = g_pos[t * 2 + 0],  p1 = g_pos[t * 2 + 1];
    float g0 = (p0 < CAP) ? g_gate[t * 2 + 0] : 0.0f;
    float g1 = (p1 < CAP) ? g_gate[t * 2 + 1] : 0.0f;
    p0 = min(p0, CAP - 1);
    p1 = min(p1, CAP - 1);
    const float4* y0 = (const float4*)(g_Ye + ((size_t)e0 * CAP + p0) * D_DIM);
    const float4* y1 = (const float4*)(g_Ye + ((size_t)e1 * CAP + p1) * D_DIM);
    float4* o = (float4*)(out + (size_t)t * D_DIM);
    for (int i = threadIdx.x; i < D_DIM / 4; i += blockDim.x) {
        float4 a = y0[i], b = y1[i], rv;
        rv.x = g0 * a.x + g1 * b.x;
        rv.y = g0 * a.y + g1 * b.y;
        rv.z = g0 * a.z + g1 * b.z;
        rv.w = g0 * a.w + g1 * b.w;
        o[i] = rv;
    }
}

// ---------------------------------------------------------------------------
// kernel_launch (graph-capturable: kernels + one memset, no allocs/syncs)
// ---------------------------------------------------------------------------
extern "C" void kernel_launch(void* const* d_in, const int* in_sizes, int n_in,
                              void* d_out, int out_size) {
    const float* x  = (const float*)d_in[0];
    const float* Wg = (const float*)d_in[1];
    const float* W1 = (const float*)d_in[2];
    const float* b1 = (const float*)d_in[3];
    const float* W2 = (const float*)d_in[4];
    const float* b2 = (const float*)d_in[5];
    float* out = (float*)d_out;

    void *xe_p, *h_p, *ye_p;
    cudaGetSymbolAddress(&xe_p, g_Xe);
    cudaGetSymbolAddress(&h_p,  g_h);
    cudaGetSymbolAddress(&ye_p, g_Ye);

    cudaMemsetAsync(xe_p, 0, sizeof(float) * (size_t)E_EXP * CAP * D_DIM);

    gate_kernel<<<T_TOK / 8, 256>>>(x, Wg);
    scan_kernel<<<1, 512>>>();
    dispatch_kernel<<<T_TOK, 256>>>(x);

    gemm_kernel<D_DIM, FF_DIM, true ><<<dim3(CAP / 128, FF_DIM / 128, E_EXP), 256>>>(
        (const float*)xe_p, W1, b1, (float*)h_p);
    gemm_kernel<FF_DIM, D_DIM, false><<<dim3(CAP / 128, D_DIM / 128, E_EXP), 256>>>(
        (const float*)h_p, W2, b2, (float*)ye_p);

    combine_kernel<<<T_TOK, 256>>>(out);
}